// round 10
// baseline (speedup 1.0000x reference)
#include <cuda_runtime.h>
#include <math.h>
#include <float.h>

// Problem constants (fixed shapes from reference setup_inputs)
#define N_ROWS 32768   // 32 * 1024
#define DIM    256
#define K_CODES 8192

#define COMMITMENT_COST 0.25

// Tiling for the argmin (1-NN) kernel
#define BM 128
#define BN 128
#define BK 8
#define LDA 132   // padded smem row stride (floats)

// -------------------- device scratch (no allocations allowed) --------------------
__device__ float  g_cnorm[K_CODES];
__device__ int    g_idx[N_ROWS];
__device__ int    g_counts[K_CODES];
__device__ double g_se;   // sum (quantized_st - x)^2
__device__ double g_sq;   // sum (quantized    - x)^2

// -------------------- f32x2 packed-FMA helpers (FFMA2) --------------------
__device__ __forceinline__ unsigned long long pk2(float x, float y) {
    unsigned long long r;
    asm("mov.b64 %0, {%1, %2};" : "=l"(r) : "f"(x), "f"(y));
    return r;
}
__device__ __forceinline__ void upk2(float& x, float& y, unsigned long long v) {
    asm("mov.b64 {%0, %1}, %2;" : "=f"(x), "=f"(y) : "l"(v));
}
__device__ __forceinline__ unsigned long long fma2(unsigned long long a,
                                                   unsigned long long b,
                                                   unsigned long long c) {
    unsigned long long d;
    asm("fma.rn.f32x2 %0, %1, %2, %3;" : "=l"(d) : "l"(a), "l"(b), "l"(c));
    return d;
}

// -------------------- kernel 1: zero scratch --------------------
__global__ void vq_zero_kernel() {
    int t = blockIdx.x * blockDim.x + threadIdx.x;
    if (t < K_CODES) g_counts[t] = 0;
    if (t == 0) { g_se = 0.0; g_sq = 0.0; }
}

// -------------------- kernel 2: 0.5*||c||^2 in fp64 (one warp per code) ---------
__global__ void vq_cnorm_kernel(const float* __restrict__ cb) {
    int gw   = (blockIdx.x * blockDim.x + threadIdx.x) >> 5;
    int lane = threadIdx.x & 31;
    if (gw >= K_CODES) return;
    const float4* row = reinterpret_cast<const float4*>(cb + (size_t)gw * DIM);
    double s = 0.0;
    #pragma unroll
    for (int q = lane; q < DIM / 4; q += 32) {
        float4 v = row[q];
        s += (double)v.x * v.x + (double)v.y * v.y
           + (double)v.z * v.z + (double)v.w * v.w;
    }
    #pragma unroll
    for (int o = 16; o; o >>= 1) s += __shfl_down_sync(0xffffffffu, s, o);
    if (lane == 0) g_cnorm[gw] = (float)(0.5 * s);
}

// -------------------- kernel 3: fused 1-NN argmin --------------------
// argmin_c ||x-c||^2  ==  argmin_c ( 0.5*||c||^2 - x.c )
// SGEMM-style 128x128 tile, BK=8, 256 threads, 8x8 microtile expressed as
// 8 rows x 4 column-pairs accumulated with fma.rn.f32x2 (FFMA2).
__global__ __launch_bounds__(256, 2)
void vq_argmin_kernel(const float* __restrict__ X, const float* __restrict__ CB) {
    // 17408 bytes: compute phase uses As/Bs/Cn; reduction phase reuses all of it.
    __shared__ __align__(16) float sm[4352];
    float* As = sm;                 // BK*LDA = 1056 floats
    float* Bs = sm + BK * LDA;      // 1056 floats
    float* Cn = sm + 2 * BK * LDA;  // 128 floats

    const int tid = threadIdx.x;
    const int tx  = tid & 15;   // column group (16)
    const int ty  = tid >> 4;   // row group (16)
    const int rowBase = blockIdx.x * BM;

    // loader mapping: each thread loads one float4 of A and one of B per chunk
    const int lr = tid >> 1;          // 0..127 (tile row)
    const int lk = (tid & 1) * 4;     // 0 or 4 (k offset within chunk)

    const float* Xp = X + (size_t)(rowBase + lr) * DIM + lk;

    float best[8];
    int   bidx[8];
    #pragma unroll
    for (int i = 0; i < 8; i++) { best[i] = FLT_MAX; bidx[i] = 0x7fffffff; }

    for (int kt = 0; kt < K_CODES / BN; ++kt) {
        const int colBase = kt * BN;
        const float* Cp = CB + (size_t)(colBase + lr) * DIM + lk;

        unsigned long long acc[8][4];
        #pragma unroll
        for (int i = 0; i < 8; i++)
            #pragma unroll
            for (int j = 0; j < 4; j++) acc[i][j] = 0ULL;

        // prefetch chunk 0
        float4 pa = *reinterpret_cast<const float4*>(Xp);
        float4 pb = *reinterpret_cast<const float4*>(Cp);

        #pragma unroll 1
        for (int ch = 0; ch < DIM / BK; ++ch) {
            __syncthreads();   // previous chunk's compute done -> safe to overwrite
            #pragma unroll
            for (int q = 0; q < 4; q++) {
                As[(lk + q) * LDA + lr] = ((const float*)&pa)[q];
                Bs[(lk + q) * LDA + lr] = ((const float*)&pb)[q];
            }
            if (ch == 0 && tid < BN) Cn[tid] = g_cnorm[colBase + tid];
            __syncthreads();
            if (ch + 1 < DIM / BK) {  // prefetch next chunk (latency hidden by compute)
                pa = *reinterpret_cast<const float4*>(Xp + (ch + 1) * BK);
                pb = *reinterpret_cast<const float4*>(Cp + (ch + 1) * BK);
            }
            #pragma unroll
            for (int k = 0; k < BK; k++) {
                const float* ak = As + k * LDA;
                const float* bk = Bs + k * LDA;
                float4 a0 = *reinterpret_cast<const float4*>(ak + ty * 4);
                float4 a1 = *reinterpret_cast<const float4*>(ak + 64 + ty * 4);
                float4 b0 = *reinterpret_cast<const float4*>(bk + tx * 4);
                float4 b1 = *reinterpret_cast<const float4*>(bk + 64 + tx * 4);
                unsigned long long bp0 = pk2(b0.x, b0.y);
                unsigned long long bp1 = pk2(b0.z, b0.w);
                unsigned long long bp2 = pk2(b1.x, b1.y);
                unsigned long long bp3 = pk2(b1.z, b1.w);
                float av[8] = {a0.x, a0.y, a0.z, a0.w, a1.x, a1.y, a1.z, a1.w};
                #pragma unroll
                for (int i = 0; i < 8; i++) {
                    unsigned long long ap = pk2(av[i], av[i]);
                    acc[i][0] = fma2(ap, bp0, acc[i][0]);
                    acc[i][1] = fma2(ap, bp1, acc[i][1]);
                    acc[i][2] = fma2(ap, bp2, acc[i][2]);
                    acc[i][3] = fma2(ap, bp3, acc[i][3]);
                }
            }
        }

        // fold this K-tile into the running (min, idx). Iteration order is
        // globally index-ascending within a thread; tie-break keeps lowest idx.
        #pragma unroll
        for (int i = 0; i < 8; i++) {
            #pragma unroll
            for (int jp = 0; jp < 4; jp++) {
                float d0, d1;
                upk2(d0, d1, acc[i][jp]);
                int nl = (jp < 2) ? (tx * 4 + jp * 2) : (64 + tx * 4 + (jp - 2) * 2);
                float s0 = Cn[nl]     - d0;
                float s1 = Cn[nl + 1] - d1;
                int   c0 = colBase + nl;
                if (s0 < best[i] || (s0 == best[i] && c0 < bidx[i]))     { best[i] = s0; bidx[i] = c0; }
                if (s1 < best[i] || (s1 == best[i] && c0 + 1 < bidx[i])) { best[i] = s1; bidx[i] = c0 + 1; }
            }
        }
    }

    // cross-thread reduction: 16 column-owning threads per row
    __syncthreads();
    float* rv = sm;                              // 128 rows * 17 (padded)
    int*   ri = reinterpret_cast<int*>(sm + 2176);
    #pragma unroll
    for (int i = 0; i < 8; i++) {
        int r = (i < 4) ? (ty * 4 + i) : (64 + ty * 4 + (i - 4));
        rv[r * 17 + tx] = best[i];
        ri[r * 17 + tx] = bidx[i];
    }
    __syncthreads();
    if (tid < BM) {
        float bv = rv[tid * 17];
        int   bi = ri[tid * 17];
        #pragma unroll
        for (int t = 1; t < 16; t++) {
            float v  = rv[tid * 17 + t];
            int   ix = ri[tid * 17 + t];
            if (v < bv || (v == bv && ix < bi)) { bv = v; bi = ix; }
        }
        g_idx[rowBase + tid] = bi;
    }
}

// -------------------- kernel 4: gather + losses + histogram + tokens -----------
// 256 threads per block, 16 rows per block (16 threads per row, float4 strided).
__global__ void vq_epilogue_kernel(const float* __restrict__ X,
                                   const float* __restrict__ CB,
                                   float* __restrict__ out_q,
                                   float* __restrict__ out_tok) {
    __shared__ float sred_e[8];
    __shared__ float sred_q[8];
    const int tid = threadIdx.x;
    const int rloc = tid >> 4;      // 0..15
    const int l16  = tid & 15;
    const int row  = blockIdx.x * 16 + rloc;

    const int idx = g_idx[row];
    const float4* xr = reinterpret_cast<const float4*>(X  + (size_t)row * DIM);
    const float4* cr = reinterpret_cast<const float4*>(CB + (size_t)idx * DIM);
    float4*       qr = reinterpret_cast<float4*>(out_q + (size_t)row * DIM);

    float e = 0.f, qd = 0.f;
    #pragma unroll
    for (int q = 0; q < 4; ++q) {
        int off = l16 + q * 16;          // float4 index 0..63
        float4 x = xr[off];
        float4 c = cr[off];
        float4 qs;
        // straight-through: qst = x + (q - x), exactly as the reference rounds it
        float t;
        t = c.x - x.x; qs.x = x.x + t; qd += t * t; { float dx = qs.x - x.x; e += dx * dx; }
        t = c.y - x.y; qs.y = x.y + t; qd += t * t; { float dx = qs.y - x.y; e += dx * dx; }
        t = c.z - x.z; qs.z = x.z + t; qd += t * t; { float dx = qs.z - x.z; e += dx * dx; }
        t = c.w - x.w; qs.w = x.w + t; qd += t * t; { float dx = qs.w - x.w; e += dx * dx; }
        qr[off] = qs;
    }
    if (l16 == 0) {
        atomicAdd(&g_counts[idx], 1);
        out_tok[row] = (float)idx;
    }
    // block reduction of the two squared-error sums
    #pragma unroll
    for (int o = 16; o; o >>= 1) {
        e  += __shfl_down_sync(0xffffffffu, e,  o);
        qd += __shfl_down_sync(0xffffffffu, qd, o);
    }
    if ((tid & 31) == 0) { sred_e[tid >> 5] = e; sred_q[tid >> 5] = qd; }
    __syncthreads();
    if (tid == 0) {
        double se = 0.0, sq = 0.0;
        #pragma unroll
        for (int w = 0; w < 8; w++) { se += (double)sred_e[w]; sq += (double)sred_q[w]; }
        atomicAdd(&g_se, se);
        atomicAdd(&g_sq, sq);
    }
}

// -------------------- kernel 5: scalars (losses + perplexity) --------------------
__global__ void vq_finalize_kernel(float* __restrict__ out_sc) {
    __shared__ double sh[256];
    int tid = threadIdx.x;
    double h = 0.0;
    for (int k = tid; k < K_CODES; k += 256) {
        double p = (double)g_counts[k] / (double)N_ROWS;
        h -= p * log(p + 1e-10);
    }
    sh[tid] = h;
    __syncthreads();
    for (int s = 128; s; s >>= 1) {
        if (tid < s) sh[tid] += sh[tid + s];
        __syncthreads();
    }
    if (tid == 0) {
        double nd = (double)N_ROWS * (double)DIM;
        double e_mse = g_se / nd;   // e_latent_loss
        double q_mse = g_sq / nd;   // q_latent_loss (codebook loss)
        float commitment = (float)(COMMITMENT_COST * e_mse);
        float codebook_l = (float)q_mse;
        float vq         = (float)(COMMITMENT_COST * e_mse + q_mse);
        float perp       = (float)exp(sh[0]);
        out_sc[0] = vq;
        out_sc[1] = commitment;
        out_sc[2] = codebook_l;
        out_sc[3] = perp;
    }
}

// -------------------- launch --------------------
extern "C" void kernel_launch(void* const* d_in, const int* in_sizes, int n_in,
                              void* d_out, int out_size) {
    const float* X  = (const float*)d_in[0];   // inputs  [32,1024,256] fp32
    const float* CB = (const float*)d_in[1];   // codebook [8192,256]  fp32
    float* out     = (float*)d_out;
    float* out_q   = out;                                  // quantized_st: 8388608
    float* out_tok = out + (size_t)N_ROWS * DIM;           // tokens:       32768
    float* out_sc  = out_tok + N_ROWS;                     // 4 scalars

    vq_zero_kernel<<<(K_CODES + 255) / 256, 256>>>();
    vq_cnorm_kernel<<<K_CODES / 8, 256>>>(CB);             // 8 warps/block, 1 code/warp
    vq_argmin_kernel<<<N_ROWS / BM, 256>>>(X, CB);         // 256 blocks
    vq_epilogue_kernel<<<N_ROWS / 16, 256>>>(X, CB, out_q, out_tok);
    vq_finalize_kernel<<<1, 256>>>(out_sc);
}

// round 11
// speedup vs baseline: 1.0010x; 1.0010x over previous
#include <cuda_runtime.h>
#include <math.h>
#include <float.h>

// Problem constants (fixed shapes from reference setup_inputs)
#define N_ROWS 32768   // 32 * 1024
#define DIM    256
#define K_CODES 8192

#define COMMITMENT_COST 0.25

// Tiling for the argmin (1-NN) kernel
#define BM 128
#define BN 128
#define BK 8
#define LDA 132   // padded smem row stride (floats)

// -------------------- device scratch (no allocations allowed) --------------------
__device__ float  g_cnorm[K_CODES];
__device__ int    g_idx[N_ROWS];
__device__ int    g_counts[K_CODES];
__device__ double g_se;   // sum (quantized_st - x)^2
__device__ double g_sq;   // sum (quantized    - x)^2

// -------------------- f32x2 packed-FMA helpers (FFMA2) --------------------
__device__ __forceinline__ unsigned long long pk2(float x, float y) {
    unsigned long long r;
    asm("mov.b64 %0, {%1, %2};" : "=l"(r) : "f"(x), "f"(y));
    return r;
}
__device__ __forceinline__ void upk2(float& x, float& y, unsigned long long v) {
    asm("mov.b64 {%0, %1}, %2;" : "=f"(x), "=f"(y) : "l"(v));
}
__device__ __forceinline__ unsigned long long fma2(unsigned long long a,
                                                   unsigned long long b,
                                                   unsigned long long c) {
    unsigned long long d;
    asm("fma.rn.f32x2 %0, %1, %2, %3;" : "=l"(d) : "l"(a), "l"(b), "l"(c));
    return d;
}

// -------------------- kernel 1: zero scratch --------------------
__global__ void vq_zero_kernel() {
    int t = blockIdx.x * blockDim.x + threadIdx.x;
    if (t < K_CODES) g_counts[t] = 0;
    if (t == 0) { g_se = 0.0; g_sq = 0.0; }
}

// -------------------- kernel 2: 0.5*||c||^2 in fp64 (one warp per code) ---------
__global__ void vq_cnorm_kernel(const float* __restrict__ cb) {
    int gw   = (blockIdx.x * blockDim.x + threadIdx.x) >> 5;
    int lane = threadIdx.x & 31;
    if (gw >= K_CODES) return;
    const float4* row = reinterpret_cast<const float4*>(cb + (size_t)gw * DIM);
    double s = 0.0;
    #pragma unroll
    for (int q = lane; q < DIM / 4; q += 32) {
        float4 v = row[q];
        s += (double)v.x * v.x + (double)v.y * v.y
           + (double)v.z * v.z + (double)v.w * v.w;
    }
    #pragma unroll
    for (int o = 16; o; o >>= 1) s += __shfl_down_sync(0xffffffffu, s, o);
    if (lane == 0) g_cnorm[gw] = (float)(0.5 * s);
}

// -------------------- kernel 3: fused 1-NN argmin --------------------
// argmin_c ||x-c||^2  ==  argmin_c ( 0.5*||c||^2 - x.c )
// SGEMM-style 128x128 tile, BK=8, 256 threads, 8x8 microtile expressed as
// 8 rows x 4 column-pairs accumulated with fma.rn.f32x2 (FFMA2).
__global__ __launch_bounds__(256, 2)
void vq_argmin_kernel(const float* __restrict__ X, const float* __restrict__ CB) {
    // 17408 bytes: compute phase uses As/Bs/Cn; reduction phase reuses all of it.
    __shared__ __align__(16) float sm[4352];
    float* As = sm;                 // BK*LDA = 1056 floats
    float* Bs = sm + BK * LDA;      // 1056 floats
    float* Cn = sm + 2 * BK * LDA;  // 128 floats

    const int tid = threadIdx.x;
    const int tx  = tid & 15;   // column group (16)
    const int ty  = tid >> 4;   // row group (16)
    const int rowBase = blockIdx.x * BM;

    // loader mapping: each thread loads one float4 of A and one of B per chunk
    const int lr = tid >> 1;          // 0..127 (tile row)
    const int lk = (tid & 1) * 4;     // 0 or 4 (k offset within chunk)

    const float* Xp = X + (size_t)(rowBase + lr) * DIM + lk;

    float best[8];
    int   bidx[8];
    #pragma unroll
    for (int i = 0; i < 8; i++) { best[i] = FLT_MAX; bidx[i] = 0x7fffffff; }

    for (int kt = 0; kt < K_CODES / BN; ++kt) {
        const int colBase = kt * BN;
        const float* Cp = CB + (size_t)(colBase + lr) * DIM + lk;

        unsigned long long acc[8][4];
        #pragma unroll
        for (int i = 0; i < 8; i++)
            #pragma unroll
            for (int j = 0; j < 4; j++) acc[i][j] = 0ULL;

        // prefetch chunk 0
        float4 pa = *reinterpret_cast<const float4*>(Xp);
        float4 pb = *reinterpret_cast<const float4*>(Cp);

        #pragma unroll 1
        for (int ch = 0; ch < DIM / BK; ++ch) {
            __syncthreads();   // previous chunk's compute done -> safe to overwrite
            #pragma unroll
            for (int q = 0; q < 4; q++) {
                As[(lk + q) * LDA + lr] = ((const float*)&pa)[q];
                Bs[(lk + q) * LDA + lr] = ((const float*)&pb)[q];
            }
            if (ch == 0 && tid < BN) Cn[tid] = g_cnorm[colBase + tid];
            __syncthreads();
            if (ch + 1 < DIM / BK) {  // prefetch next chunk (latency hidden by compute)
                pa = *reinterpret_cast<const float4*>(Xp + (ch + 1) * BK);
                pb = *reinterpret_cast<const float4*>(Cp + (ch + 1) * BK);
            }
            #pragma unroll
            for (int k = 0; k < BK; k++) {
                const float* ak = As + k * LDA;
                const float* bk = Bs + k * LDA;
                float4 a0 = *reinterpret_cast<const float4*>(ak + ty * 4);
                float4 a1 = *reinterpret_cast<const float4*>(ak + 64 + ty * 4);
                float4 b0 = *reinterpret_cast<const float4*>(bk + tx * 4);
                float4 b1 = *reinterpret_cast<const float4*>(bk + 64 + tx * 4);
                unsigned long long bp0 = pk2(b0.x, b0.y);
                unsigned long long bp1 = pk2(b0.z, b0.w);
                unsigned long long bp2 = pk2(b1.x, b1.y);
                unsigned long long bp3 = pk2(b1.z, b1.w);
                float av[8] = {a0.x, a0.y, a0.z, a0.w, a1.x, a1.y, a1.z, a1.w};
                #pragma unroll
                for (int i = 0; i < 8; i++) {
                    unsigned long long ap = pk2(av[i], av[i]);
                    acc[i][0] = fma2(ap, bp0, acc[i][0]);
                    acc[i][1] = fma2(ap, bp1, acc[i][1]);
                    acc[i][2] = fma2(ap, bp2, acc[i][2]);
                    acc[i][3] = fma2(ap, bp3, acc[i][3]);
                }
            }
        }

        // fold this K-tile into the running (min, idx). Iteration order is
        // globally index-ascending within a thread; tie-break keeps lowest idx.
        #pragma unroll
        for (int i = 0; i < 8; i++) {
            #pragma unroll
            for (int jp = 0; jp < 4; jp++) {
                float d0, d1;
                upk2(d0, d1, acc[i][jp]);
                int nl = (jp < 2) ? (tx * 4 + jp * 2) : (64 + tx * 4 + (jp - 2) * 2);
                float s0 = Cn[nl]     - d0;
                float s1 = Cn[nl + 1] - d1;
                int   c0 = colBase + nl;
                if (s0 < best[i] || (s0 == best[i] && c0 < bidx[i]))     { best[i] = s0; bidx[i] = c0; }
                if (s1 < best[i] || (s1 == best[i] && c0 + 1 < bidx[i])) { best[i] = s1; bidx[i] = c0 + 1; }
            }
        }
    }

    // cross-thread reduction: 16 column-owning threads per row
    __syncthreads();
    float* rv = sm;                              // 128 rows * 17 (padded)
    int*   ri = reinterpret_cast<int*>(sm + 2176);
    #pragma unroll
    for (int i = 0; i < 8; i++) {
        int r = (i < 4) ? (ty * 4 + i) : (64 + ty * 4 + (i - 4));
        rv[r * 17 + tx] = best[i];
        ri[r * 17 + tx] = bidx[i];
    }
    __syncthreads();
    if (tid < BM) {
        float bv = rv[tid * 17];
        int   bi = ri[tid * 17];
        #pragma unroll
        for (int t = 1; t < 16; t++) {
            float v  = rv[tid * 17 + t];
            int   ix = ri[tid * 17 + t];
            if (v < bv || (v == bv && ix < bi)) { bv = v; bi = ix; }
        }
        g_idx[rowBase + tid] = bi;
    }
}

// -------------------- kernel 4: gather + losses + histogram + tokens -----------
// 256 threads per block, 16 rows per block (16 threads per row, float4 strided).
__global__ void vq_epilogue_kernel(const float* __restrict__ X,
                                   const float* __restrict__ CB,
                                   float* __restrict__ out_q,
                                   float* __restrict__ out_tok) {
    __shared__ float sred_e[8];
    __shared__ float sred_q[8];
    const int tid = threadIdx.x;
    const int rloc = tid >> 4;      // 0..15
    const int l16  = tid & 15;
    const int row  = blockIdx.x * 16 + rloc;

    const int idx = g_idx[row];
    const float4* xr = reinterpret_cast<const float4*>(X  + (size_t)row * DIM);
    const float4* cr = reinterpret_cast<const float4*>(CB + (size_t)idx * DIM);
    float4*       qr = reinterpret_cast<float4*>(out_q + (size_t)row * DIM);

    float e = 0.f, qd = 0.f;
    #pragma unroll
    for (int q = 0; q < 4; ++q) {
        int off = l16 + q * 16;          // float4 index 0..63
        float4 x = xr[off];
        float4 c = cr[off];
        float4 qs;
        // straight-through: qst = x + (q - x), exactly as the reference rounds it
        float t;
        t = c.x - x.x; qs.x = x.x + t; qd += t * t; { float dx = qs.x - x.x; e += dx * dx; }
        t = c.y - x.y; qs.y = x.y + t; qd += t * t; { float dx = qs.y - x.y; e += dx * dx; }
        t = c.z - x.z; qs.z = x.z + t; qd += t * t; { float dx = qs.z - x.z; e += dx * dx; }
        t = c.w - x.w; qs.w = x.w + t; qd += t * t; { float dx = qs.w - x.w; e += dx * dx; }
        qr[off] = qs;
    }
    if (l16 == 0) {
        atomicAdd(&g_counts[idx], 1);
        out_tok[row] = (float)idx;
    }
    // block reduction of the two squared-error sums
    #pragma unroll
    for (int o = 16; o; o >>= 1) {
        e  += __shfl_down_sync(0xffffffffu, e,  o);
        qd += __shfl_down_sync(0xffffffffu, qd, o);
    }
    if ((tid & 31) == 0) { sred_e[tid >> 5] = e; sred_q[tid >> 5] = qd; }
    __syncthreads();
    if (tid == 0) {
        double se = 0.0, sq = 0.0;
        #pragma unroll
        for (int w = 0; w < 8; w++) { se += (double)sred_e[w]; sq += (double)sred_q[w]; }
        atomicAdd(&g_se, se);
        atomicAdd(&g_sq, sq);
    }
}

// -------------------- kernel 5: scalars (losses + perplexity) --------------------
__global__ void vq_finalize_kernel(float* __restrict__ out_sc) {
    __shared__ double sh[256];
    int tid = threadIdx.x;
    double h = 0.0;
    for (int k = tid; k < K_CODES; k += 256) {
        double p = (double)g_counts[k] / (double)N_ROWS;
        h -= p * log(p + 1e-10);
    }
    sh[tid] = h;
    __syncthreads();
    for (int s = 128; s; s >>= 1) {
        if (tid < s) sh[tid] += sh[tid + s];
        __syncthreads();
    }
    if (tid == 0) {
        double nd = (double)N_ROWS * (double)DIM;
        double e_mse = g_se / nd;   // e_latent_loss
        double q_mse = g_sq / nd;   // q_latent_loss (codebook loss)
        float commitment = (float)(COMMITMENT_COST * e_mse);
        float codebook_l = (float)q_mse;
        float vq         = (float)(COMMITMENT_COST * e_mse + q_mse);
        float perp       = (float)exp(sh[0]);
        out_sc[0] = vq;
        out_sc[1] = commitment;
        out_sc[2] = codebook_l;
        out_sc[3] = perp;
    }
}

// -------------------- launch --------------------
extern "C" void kernel_launch(void* const* d_in, const int* in_sizes, int n_in,
                              void* d_out, int out_size) {
    const float* X  = (const float*)d_in[0];   // inputs  [32,1024,256] fp32
    const float* CB = (const float*)d_in[1];   // codebook [8192,256]  fp32
    float* out     = (float*)d_out;
    float* out_q   = out;                                  // quantized_st: 8388608
    float* out_tok = out + (size_t)N_ROWS * DIM;           // tokens:       32768
    float* out_sc  = out_tok + N_ROWS;                     // 4 scalars

    vq_zero_kernel<<<(K_CODES + 255) / 256, 256>>>();
    vq_cnorm_kernel<<<K_CODES / 8, 256>>>(CB);             // 8 warps/block, 1 code/warp
    vq_argmin_kernel<<<N_ROWS / BM, 256>>>(X, CB);         // 256 blocks
    vq_epilogue_kernel<<<N_ROWS / 16, 256>>>(X, CB, out_q, out_tok);
    vq_finalize_kernel<<<1, 256>>>(out_sc);
}

// round 12
// speedup vs baseline: 1.0019x; 1.0009x over previous
#include <cuda_runtime.h>
#include <math.h>
#include <float.h>

// Problem constants (fixed shapes from reference setup_inputs)
#define N_ROWS 32768   // 32 * 1024
#define DIM    256
#define K_CODES 8192

#define COMMITMENT_COST 0.25

// Tiling for the argmin (1-NN) kernel
#define BM 128
#define BN 128
#define BK 8
#define LDA 132   // padded smem row stride (floats)

// -------------------- device scratch (no allocations allowed) --------------------
__device__ float  g_cnorm[K_CODES];
__device__ int    g_idx[N_ROWS];
__device__ int    g_counts[K_CODES];
__device__ double g_se;   // sum (quantized_st - x)^2
__device__ double g_sq;   // sum (quantized    - x)^2

// -------------------- f32x2 packed-FMA helpers (FFMA2) --------------------
__device__ __forceinline__ unsigned long long pk2(float x, float y) {
    unsigned long long r;
    asm("mov.b64 %0, {%1, %2};" : "=l"(r) : "f"(x), "f"(y));
    return r;
}
__device__ __forceinline__ void upk2(float& x, float& y, unsigned long long v) {
    asm("mov.b64 {%0, %1}, %2;" : "=f"(x), "=f"(y) : "l"(v));
}
__device__ __forceinline__ unsigned long long fma2(unsigned long long a,
                                                   unsigned long long b,
                                                   unsigned long long c) {
    unsigned long long d;
    asm("fma.rn.f32x2 %0, %1, %2, %3;" : "=l"(d) : "l"(a), "l"(b), "l"(c));
    return d;
}

// -------------------- kernel 1: zero scratch --------------------
__global__ void vq_zero_kernel() {
    int t = blockIdx.x * blockDim.x + threadIdx.x;
    if (t < K_CODES) g_counts[t] = 0;
    if (t == 0) { g_se = 0.0; g_sq = 0.0; }
}

// -------------------- kernel 2: 0.5*||c||^2 in fp64 (one warp per code) ---------
__global__ void vq_cnorm_kernel(const float* __restrict__ cb) {
    int gw   = (blockIdx.x * blockDim.x + threadIdx.x) >> 5;
    int lane = threadIdx.x & 31;
    if (gw >= K_CODES) return;
    const float4* row = reinterpret_cast<const float4*>(cb + (size_t)gw * DIM);
    double s = 0.0;
    #pragma unroll
    for (int q = lane; q < DIM / 4; q += 32) {
        float4 v = row[q];
        s += (double)v.x * v.x + (double)v.y * v.y
           + (double)v.z * v.z + (double)v.w * v.w;
    }
    #pragma unroll
    for (int o = 16; o; o >>= 1) s += __shfl_down_sync(0xffffffffu, s, o);
    if (lane == 0) g_cnorm[gw] = (float)(0.5 * s);
}

// -------------------- kernel 3: fused 1-NN argmin --------------------
// argmin_c ||x-c||^2  ==  argmin_c ( 0.5*||c||^2 - x.c )
// SGEMM-style 128x128 tile, BK=8, 256 threads, 8x8 microtile expressed as
// 8 rows x 4 column-pairs accumulated with fma.rn.f32x2 (FFMA2).
__global__ __launch_bounds__(256, 2)
void vq_argmin_kernel(const float* __restrict__ X, const float* __restrict__ CB) {
    // 17408 bytes: compute phase uses As/Bs/Cn; reduction phase reuses all of it.
    __shared__ __align__(16) float sm[4352];
    float* As = sm;                 // BK*LDA = 1056 floats
    float* Bs = sm + BK * LDA;      // 1056 floats
    float* Cn = sm + 2 * BK * LDA;  // 128 floats

    const int tid = threadIdx.x;
    const int tx  = tid & 15;   // column group (16)
    const int ty  = tid >> 4;   // row group (16)
    const int rowBase = blockIdx.x * BM;

    // loader mapping: each thread loads one float4 of A and one of B per chunk
    const int lr = tid >> 1;          // 0..127 (tile row)
    const int lk = (tid & 1) * 4;     // 0 or 4 (k offset within chunk)

    const float* Xp = X + (size_t)(rowBase + lr) * DIM + lk;

    float best[8];
    int   bidx[8];
    #pragma unroll
    for (int i = 0; i < 8; i++) { best[i] = FLT_MAX; bidx[i] = 0x7fffffff; }

    for (int kt = 0; kt < K_CODES / BN; ++kt) {
        const int colBase = kt * BN;
        const float* Cp = CB + (size_t)(colBase + lr) * DIM + lk;

        unsigned long long acc[8][4];
        #pragma unroll
        for (int i = 0; i < 8; i++)
            #pragma unroll
            for (int j = 0; j < 4; j++) acc[i][j] = 0ULL;

        // prefetch chunk 0
        float4 pa = *reinterpret_cast<const float4*>(Xp);
        float4 pb = *reinterpret_cast<const float4*>(Cp);

        #pragma unroll 1
        for (int ch = 0; ch < DIM / BK; ++ch) {
            __syncthreads();   // previous chunk's compute done -> safe to overwrite
            #pragma unroll
            for (int q = 0; q < 4; q++) {
                As[(lk + q) * LDA + lr] = ((const float*)&pa)[q];
                Bs[(lk + q) * LDA + lr] = ((const float*)&pb)[q];
            }
            if (ch == 0 && tid < BN) Cn[tid] = g_cnorm[colBase + tid];
            __syncthreads();
            if (ch + 1 < DIM / BK) {  // prefetch next chunk (latency hidden by compute)
                pa = *reinterpret_cast<const float4*>(Xp + (ch + 1) * BK);
                pb = *reinterpret_cast<const float4*>(Cp + (ch + 1) * BK);
            }
            #pragma unroll
            for (int k = 0; k < BK; k++) {
                const float* ak = As + k * LDA;
                const float* bk = Bs + k * LDA;
                float4 a0 = *reinterpret_cast<const float4*>(ak + ty * 4);
                float4 a1 = *reinterpret_cast<const float4*>(ak + 64 + ty * 4);
                float4 b0 = *reinterpret_cast<const float4*>(bk + tx * 4);
                float4 b1 = *reinterpret_cast<const float4*>(bk + 64 + tx * 4);
                unsigned long long bp0 = pk2(b0.x, b0.y);
                unsigned long long bp1 = pk2(b0.z, b0.w);
                unsigned long long bp2 = pk2(b1.x, b1.y);
                unsigned long long bp3 = pk2(b1.z, b1.w);
                float av[8] = {a0.x, a0.y, a0.z, a0.w, a1.x, a1.y, a1.z, a1.w};
                #pragma unroll
                for (int i = 0; i < 8; i++) {
                    unsigned long long ap = pk2(av[i], av[i]);
                    acc[i][0] = fma2(ap, bp0, acc[i][0]);
                    acc[i][1] = fma2(ap, bp1, acc[i][1]);
                    acc[i][2] = fma2(ap, bp2, acc[i][2]);
                    acc[i][3] = fma2(ap, bp3, acc[i][3]);
                }
            }
        }

        // fold this K-tile into the running (min, idx). Iteration order is
        // globally index-ascending within a thread; tie-break keeps lowest idx.
        #pragma unroll
        for (int i = 0; i < 8; i++) {
            #pragma unroll
            for (int jp = 0; jp < 4; jp++) {
                float d0, d1;
                upk2(d0, d1, acc[i][jp]);
                int nl = (jp < 2) ? (tx * 4 + jp * 2) : (64 + tx * 4 + (jp - 2) * 2);
                float s0 = Cn[nl]     - d0;
                float s1 = Cn[nl + 1] - d1;
                int   c0 = colBase + nl;
                if (s0 < best[i] || (s0 == best[i] && c0 < bidx[i]))     { best[i] = s0; bidx[i] = c0; }
                if (s1 < best[i] || (s1 == best[i] && c0 + 1 < bidx[i])) { best[i] = s1; bidx[i] = c0 + 1; }
            }
        }
    }

    // cross-thread reduction: 16 column-owning threads per row
    __syncthreads();
    float* rv = sm;                              // 128 rows * 17 (padded)
    int*   ri = reinterpret_cast<int*>(sm + 2176);
    #pragma unroll
    for (int i = 0; i < 8; i++) {
        int r = (i < 4) ? (ty * 4 + i) : (64 + ty * 4 + (i - 4));
        rv[r * 17 + tx] = best[i];
        ri[r * 17 + tx] = bidx[i];
    }
    __syncthreads();
    if (tid < BM) {
        float bv = rv[tid * 17];
        int   bi = ri[tid * 17];
        #pragma unroll
        for (int t = 1; t < 16; t++) {
            float v  = rv[tid * 17 + t];
            int   ix = ri[tid * 17 + t];
            if (v < bv || (v == bv && ix < bi)) { bv = v; bi = ix; }
        }
        g_idx[rowBase + tid] = bi;
    }
}

// -------------------- kernel 4: gather + losses + histogram + tokens -----------
// 256 threads per block, 16 rows per block (16 threads per row, float4 strided).
__global__ void vq_epilogue_kernel(const float* __restrict__ X,
                                   const float* __restrict__ CB,
                                   float* __restrict__ out_q,
                                   float* __restrict__ out_tok) {
    __shared__ float sred_e[8];
    __shared__ float sred_q[8];
    const int tid = threadIdx.x;
    const int rloc = tid >> 4;      // 0..15
    const int l16  = tid & 15;
    const int row  = blockIdx.x * 16 + rloc;

    const int idx = g_idx[row];
    const float4* xr = reinterpret_cast<const float4*>(X  + (size_t)row * DIM);
    const float4* cr = reinterpret_cast<const float4*>(CB + (size_t)idx * DIM);
    float4*       qr = reinterpret_cast<float4*>(out_q + (size_t)row * DIM);

    float e = 0.f, qd = 0.f;
    #pragma unroll
    for (int q = 0; q < 4; ++q) {
        int off = l16 + q * 16;          // float4 index 0..63
        float4 x = xr[off];
        float4 c = cr[off];
        float4 qs;
        // straight-through: qst = x + (q - x), exactly as the reference rounds it
        float t;
        t = c.x - x.x; qs.x = x.x + t; qd += t * t; { float dx = qs.x - x.x; e += dx * dx; }
        t = c.y - x.y; qs.y = x.y + t; qd += t * t; { float dx = qs.y - x.y; e += dx * dx; }
        t = c.z - x.z; qs.z = x.z + t; qd += t * t; { float dx = qs.z - x.z; e += dx * dx; }
        t = c.w - x.w; qs.w = x.w + t; qd += t * t; { float dx = qs.w - x.w; e += dx * dx; }
        qr[off] = qs;
    }
    if (l16 == 0) {
        atomicAdd(&g_counts[idx], 1);
        out_tok[row] = (float)idx;
    }
    // block reduction of the two squared-error sums
    #pragma unroll
    for (int o = 16; o; o >>= 1) {
        e  += __shfl_down_sync(0xffffffffu, e,  o);
        qd += __shfl_down_sync(0xffffffffu, qd, o);
    }
    if ((tid & 31) == 0) { sred_e[tid >> 5] = e; sred_q[tid >> 5] = qd; }
    __syncthreads();
    if (tid == 0) {
        double se = 0.0, sq = 0.0;
        #pragma unroll
        for (int w = 0; w < 8; w++) { se += (double)sred_e[w]; sq += (double)sred_q[w]; }
        atomicAdd(&g_se, se);
        atomicAdd(&g_sq, sq);
    }
}

// -------------------- kernel 5: scalars (losses + perplexity) --------------------
__global__ void vq_finalize_kernel(float* __restrict__ out_sc) {
    __shared__ double sh[256];
    int tid = threadIdx.x;
    double h = 0.0;
    for (int k = tid; k < K_CODES; k += 256) {
        double p = (double)g_counts[k] / (double)N_ROWS;
        h -= p * log(p + 1e-10);
    }
    sh[tid] = h;
    __syncthreads();
    for (int s = 128; s; s >>= 1) {
        if (tid < s) sh[tid] += sh[tid + s];
        __syncthreads();
    }
    if (tid == 0) {
        double nd = (double)N_ROWS * (double)DIM;
        double e_mse = g_se / nd;   // e_latent_loss
        double q_mse = g_sq / nd;   // q_latent_loss (codebook loss)
        float commitment = (float)(COMMITMENT_COST * e_mse);
        float codebook_l = (float)q_mse;
        float vq         = (float)(COMMITMENT_COST * e_mse + q_mse);
        float perp       = (float)exp(sh[0]);
        out_sc[0] = vq;
        out_sc[1] = commitment;
        out_sc[2] = codebook_l;
        out_sc[3] = perp;
    }
}

// -------------------- launch --------------------
extern "C" void kernel_launch(void* const* d_in, const int* in_sizes, int n_in,
                              void* d_out, int out_size) {
    const float* X  = (const float*)d_in[0];   // inputs  [32,1024,256] fp32
    const float* CB = (const float*)d_in[1];   // codebook [8192,256]  fp32
    float* out     = (float*)d_out;
    float* out_q   = out;                                  // quantized_st: 8388608
    float* out_tok = out + (size_t)N_ROWS * DIM;           // tokens:       32768
    float* out_sc  = out_tok + N_ROWS;                     // 4 scalars

    vq_zero_kernel<<<(K_CODES + 255) / 256, 256>>>();
    vq_cnorm_kernel<<<K_CODES / 8, 256>>>(CB);             // 8 warps/block, 1 code/warp
    vq_argmin_kernel<<<N_ROWS / BM, 256>>>(X, CB);         // 256 blocks
    vq_epilogue_kernel<<<N_ROWS / 16, 256>>>(X, CB, out_q, out_tok);
    vq_finalize_kernel<<<1, 256>>>(out_sc);
}

// round 17
// speedup vs baseline: 1.3414x; 1.3389x over previous
#include <cuda_runtime.h>
#include <cuda_fp16.h>
#include <math.h>
#include <float.h>
#include <stdint.h>

// Problem constants
#define N_ROWS 32768   // 32 * 1024
#define DIM    256
#define K_CODES 8192
#define COMMITMENT_COST 0.25

// ===================== device scratch (static — no allocations) ==============
__device__ float  g_cnorm[K_CODES];                 // 0.5*||c||^2 (fp64-accurate)
__device__ unsigned long long g_best[N_ROWS];       // packed (sortable score | idx)
__device__ int    g_counts[K_CODES];
__device__ double g_se;
__device__ double g_sq;
__device__ __align__(16) __half g_xh[N_ROWS * DIM];   // 16 MB
__device__ __align__(16) __half g_xl[N_ROWS * DIM];   // 16 MB
__device__ __align__(16) __half g_ch[K_CODES * DIM];  // 4 MB
__device__ __align__(16) __half g_cl[K_CODES * DIM];  // 4 MB

// ===================== small helpers =========================================
__device__ __forceinline__ uint32_t smem_to_u32(const void* smem_ptr) {
    uint32_t addr;
    asm("{ .reg .u64 tmp; cvta.to.shared.u64 tmp, %1; cvt.u32.u64 %0, tmp; }"
        : "=r"(addr) : "l"(smem_ptr));
    return addr;
}
__device__ __forceinline__ void ldsm4(uint32_t r[4], uint32_t addr) {
    asm volatile("ldmatrix.sync.aligned.m8n8.x4.shared.b16 {%0,%1,%2,%3}, [%4];"
        : "=r"(r[0]), "=r"(r[1]), "=r"(r[2]), "=r"(r[3]) : "r"(addr));
}
__device__ __forceinline__ void mma16816(float c[4], const uint32_t a[4],
                                         const uint32_t b[2]) {
    asm volatile(
        "mma.sync.aligned.m16n8k16.row.col.f32.f16.f16.f32 "
        "{%0,%1,%2,%3}, {%4,%5,%6,%7}, {%8,%9}, {%0,%1,%2,%3};"
        : "+f"(c[0]), "+f"(c[1]), "+f"(c[2]), "+f"(c[3])
        : "r"(a[0]), "r"(a[1]), "r"(a[2]), "r"(a[3]), "r"(b[0]), "r"(b[1]));
}
__device__ __forceinline__ void cpasync16(uint32_t dst, const void* src) {
    asm volatile("cp.async.cg.shared.global [%0], [%1], 16;" :: "r"(dst), "l"(src));
}
#define CP_COMMIT() asm volatile("cp.async.commit_group;" ::: "memory")

// ===================== kernel 1: zero / init scratch =========================
__global__ void vq_zero_kernel() {
    int t = blockIdx.x * blockDim.x + threadIdx.x;
    if (t < N_ROWS)  g_best[t] = 0xFFFFFFFFFFFFFFFFull;
    if (t < K_CODES) g_counts[t] = 0;
    if (t == 0) { g_se = 0.0; g_sq = 0.0; }
}

// ===================== kernel 2: 0.5*||c||^2 in fp64 =========================
__global__ void vq_cnorm_kernel(const float* __restrict__ cb) {
    int gw   = (blockIdx.x * blockDim.x + threadIdx.x) >> 5;
    int lane = threadIdx.x & 31;
    if (gw >= K_CODES) return;
    const float4* row = reinterpret_cast<const float4*>(cb + (size_t)gw * DIM);
    double s = 0.0;
    #pragma unroll
    for (int q = lane; q < DIM / 4; q += 32) {
        float4 v = row[q];
        s += (double)v.x * v.x + (double)v.y * v.y
           + (double)v.z * v.z + (double)v.w * v.w;
    }
    #pragma unroll
    for (int o = 16; o; o >>= 1) s += __shfl_down_sync(0xffffffffu, s, o);
    if (lane == 0) g_cnorm[gw] = (float)(0.5 * s);
}

// ===================== kernels 3a/3b: fp16 2-term split ======================
// x = h + l with fp16 h,l: residual <= 2^-24 relative (fp32-equivalent).
// IMPORTANT: destination planes are referenced directly in DEVICE code —
// passing __device__ symbol addresses from host silently writes host memory
// via ATS on GB300 (the Round-15 bug).
__device__ __forceinline__ void split_store(const float* __restrict__ src,
                                            __half* __restrict__ hdst,
                                            __half* __restrict__ ldst, int t) {
    float4 v = reinterpret_cast<const float4*>(src)[t];
    __half h[4], l[4];
    const float* f = (const float*)&v;
    #pragma unroll
    for (int i = 0; i < 4; ++i) {
        h[i] = __float2half_rn(f[i]);
        l[i] = __float2half_rn(f[i] - __half2float(h[i]));
    }
    uint2 hv, lv;
    hv.x = ((uint32_t)__half_as_ushort(h[1]) << 16) | __half_as_ushort(h[0]);
    hv.y = ((uint32_t)__half_as_ushort(h[3]) << 16) | __half_as_ushort(h[2]);
    lv.x = ((uint32_t)__half_as_ushort(l[1]) << 16) | __half_as_ushort(l[0]);
    lv.y = ((uint32_t)__half_as_ushort(l[3]) << 16) | __half_as_ushort(l[2]);
    reinterpret_cast<uint2*>(hdst)[t] = hv;
    reinterpret_cast<uint2*>(ldst)[t] = lv;
}
__global__ void vq_split_x_kernel(const float* __restrict__ X) {
    int t = blockIdx.x * blockDim.x + threadIdx.x;
    if (t < N_ROWS * DIM / 4) split_store(X, g_xh, g_xl, t);
}
__global__ void vq_split_c_kernel(const float* __restrict__ CB) {
    int t = blockIdx.x * blockDim.x + threadIdx.x;
    if (t < K_CODES * DIM / 4) split_store(CB, g_ch, g_cl, t);
}

// ===================== kernel 4: mma.sync fused 1-NN argmin ==================
// argmin_c ||x-c||^2 == argmin_c (0.5||c||^2 - x.c).
// x.c = hh + hl + lh + ll (each product exact; fp32 accumulator).
// CTA: 128 rows x 2048 cols (16 col-tiles of 128). Warp grid 2x4 (64x32 each).
// Smem stage = [A:128x(32h|32l) | B:128x(32h|32l)] fp16, 128B rows,
// SW128 xor swizzle; cp.async double-buffered; ldmatrix reads.
#define STAGE_BYTES 32768
#define AOFF 0
#define BOFF 16384
#define CNOFF (2 * STAGE_BYTES)
#define ARG_SMEM (CNOFF + 512)

__global__ __launch_bounds__(256, 1) void vq_argmin_mma() {
    extern __shared__ __align__(16) char sm[];
    const uint32_t smb = smem_to_u32(sm);
    float* cn_s = reinterpret_cast<float*>(sm + CNOFF);

    const int tid   = threadIdx.x;
    const int lane  = tid & 31;
    const int wid   = tid >> 5;
    const int warpM = wid >> 2;    // 0..1  (64 rows each)
    const int warpN = wid & 3;     // 0..3  (32 cols each)
    const int rowBase = (int)(blockIdx.x >> 2) * 128;
    const int ce      = (int)(blockIdx.x & 3);

    // ---- loader mapping: thread covers half a 128B smem row (h or l half) ----
    const int ldRow = tid >> 1;
    const int sel   = tid & 1;                     // 0: h-plane, 1: l-plane
    const __half* srcA = (sel ? g_xl : g_xh) + (size_t)(rowBase + ldRow) * DIM;
    const __half* srcBplane = sel ? g_cl : g_ch;
    uint32_t dcol[4];
    {
        uint32_t sw = (uint32_t)((ldRow & 7) << 4);
        #pragma unroll
        for (int q = 0; q < 4; ++q)
            dcol[q] = ((uint32_t)(sel * 64 + q * 16)) ^ sw;
    }
    const uint32_t dRowA = (uint32_t)(AOFF + ldRow * 128);
    const uint32_t dRowB = (uint32_t)(BOFF + ldRow * 128);

    // ---- ldmatrix per-lane constants ----
    const int aRow = warpM * 64 + (lane & 15);           // + mi*16
    const uint32_t aKe = (uint32_t)(((lane >> 4) & 1) * 16);
    const int bRow0 = warpN * 32 + (lane & 7) + ((lane >> 4) & 1) * 8;  // + p*16
    const uint32_t bKe = (uint32_t)(((lane >> 3) & 1) * 16);

    float bestv[8];
    int   besti[8];
    #pragma unroll
    for (int i = 0; i < 8; ++i) { bestv[i] = FLT_MAX; besti[i] = 0; }

    for (int ctl = 0; ctl < 16; ++ctl) {
        const int colBase = (ce * 16 + ctl) * 128;
        __syncthreads();                       // cn_s readers from prior tile done
        if (tid < 128) cn_s[tid] = g_cnorm[colBase + tid];

        float acc[4][4][4];
        #pragma unroll
        for (int mi = 0; mi < 4; ++mi)
            #pragma unroll
            for (int ni = 0; ni < 4; ++ni)
                #pragma unroll
                for (int j = 0; j < 4; ++j) acc[mi][ni][j] = 0.f;

        const __half* srcB = srcBplane + (size_t)(colBase + ldRow) * DIM;

        // prefetch stage 0
        {
            #pragma unroll
            for (int q = 0; q < 4; ++q) {
                cpasync16(smb + dRowA + dcol[q], srcA + q * 8);
                cpasync16(smb + dRowB + dcol[q], srcB + q * 8);
            }
            CP_COMMIT();
        }

        #pragma unroll 1
        for (int st = 0; st < 8; ++st) {
            if (st < 7) {
                const uint32_t nb = smb + (((st + 1) & 1) ? STAGE_BYTES : 0);
                const __half* sa = srcA + (st + 1) * 32;
                const __half* sb = srcB + (st + 1) * 32;
                #pragma unroll
                for (int q = 0; q < 4; ++q) {
                    cpasync16(nb + dRowA + dcol[q], sa + q * 8);
                    cpasync16(nb + dRowB + dcol[q], sb + q * 8);
                }
                CP_COMMIT();
                asm volatile("cp.async.wait_group 1;" ::: "memory");
            } else {
                asm volatile("cp.async.wait_group 0;" ::: "memory");
            }
            __syncthreads();

            const uint32_t cb = smb + ((st & 1) ? STAGE_BYTES : 0);
            #pragma unroll
            for (int ks = 0; ks < 2; ++ks) {
                const uint32_t kb = (uint32_t)(ks * 32);
                uint32_t ah[4][4], al[4][4];
                #pragma unroll
                for (int mi = 0; mi < 4; ++mi) {
                    int r = aRow + mi * 16;
                    uint32_t rb = cb + AOFF + (uint32_t)(r * 128);
                    uint32_t sw = (uint32_t)((r & 7) << 4);
                    ldsm4(ah[mi], rb + ((kb + aKe) ^ sw));
                    ldsm4(al[mi], rb + ((64u + kb + aKe) ^ sw));
                }
                uint32_t bh[4][2], bl[4][2];
                #pragma unroll
                for (int p = 0; p < 2; ++p) {
                    int r = bRow0 + p * 16;
                    uint32_t rb = cb + BOFF + (uint32_t)(r * 128);
                    uint32_t sw = (uint32_t)((r & 7) << 4);
                    uint32_t t0[4], t1[4];
                    ldsm4(t0, rb + ((kb + bKe) ^ sw));
                    ldsm4(t1, rb + ((64u + kb + bKe) ^ sw));
                    bh[2 * p][0] = t0[0]; bh[2 * p][1] = t0[1];
                    bh[2 * p + 1][0] = t0[2]; bh[2 * p + 1][1] = t0[3];
                    bl[2 * p][0] = t1[0]; bl[2 * p][1] = t1[1];
                    bl[2 * p + 1][0] = t1[2]; bl[2 * p + 1][1] = t1[3];
                }
                #pragma unroll
                for (int mi = 0; mi < 4; ++mi)
                    #pragma unroll
                    for (int ni = 0; ni < 4; ++ni) {
                        mma16816(acc[mi][ni], ah[mi], bh[ni]);
                        mma16816(acc[mi][ni], ah[mi], bl[ni]);
                        mma16816(acc[mi][ni], al[mi], bh[ni]);
                        mma16816(acc[mi][ni], al[mi], bl[ni]);
                    }
            }
            __syncthreads();   // compute done before next prefetch overwrites
        }

        // ---- fold this 128-col tile into per-thread running (min, idx) ----
        const int tig2 = (lane & 3) * 2;
        #pragma unroll
        for (int mi = 0; mi < 4; ++mi) {
            #pragma unroll
            for (int ni = 0; ni < 4; ++ni) {
                int cl = warpN * 32 + ni * 8 + tig2;
                float cn0 = cn_s[cl], cn1 = cn_s[cl + 1];
                int gi = colBase + cl;
                float s00 = cn0 - acc[mi][ni][0];
                float s01 = cn1 - acc[mi][ni][1];
                float s10 = cn0 - acc[mi][ni][2];
                float s11 = cn1 - acc[mi][ni][3];
                int s0 = mi * 2, s1 = mi * 2 + 1;
                if (s00 < bestv[s0]) { bestv[s0] = s00; besti[s0] = gi; }
                if (s01 < bestv[s0]) { bestv[s0] = s01; besti[s0] = gi + 1; }
                if (s10 < bestv[s1]) { bestv[s1] = s10; besti[s1] = gi; }
                if (s11 < bestv[s1]) { bestv[s1] = s11; besti[s1] = gi + 1; }
            }
        }
    }

    // ---- global fold: packed sortable-float | idx, atomicMin ----
    #pragma unroll
    for (int mi = 0; mi < 4; ++mi) {
        #pragma unroll
        for (int h = 0; h < 2; ++h) {
            int row = rowBase + warpM * 64 + mi * 16 + (lane >> 2) + h * 8;
            int slot = mi * 2 + h;
            uint32_t u = __float_as_uint(bestv[slot]);
            u = (u & 0x80000000u) ? ~u : (u | 0x80000000u);
            unsigned long long pack =
                ((unsigned long long)u << 32) | (uint32_t)besti[slot];
            atomicMin(&g_best[row], pack);
        }
    }
}

// ===================== kernel 5: gather + losses + histogram + tokens ========
__global__ void vq_epilogue_kernel(const float* __restrict__ X,
                                   const float* __restrict__ CB,
                                   float* __restrict__ out_q,
                                   float* __restrict__ out_tok) {
    __shared__ float sred_e[8];
    __shared__ float sred_q[8];
    const int tid = threadIdx.x;
    const int rloc = tid >> 4;
    const int l16  = tid & 15;
    const int row  = blockIdx.x * 16 + rloc;

    const int idx = (int)(g_best[row] & 0xFFFFFFFFull);
    const float4* xr = reinterpret_cast<const float4*>(X  + (size_t)row * DIM);
    const float4* cr = reinterpret_cast<const float4*>(CB + (size_t)idx * DIM);
    float4*       qr = reinterpret_cast<float4*>(out_q + (size_t)row * DIM);

    float e = 0.f, qd = 0.f;
    #pragma unroll
    for (int q = 0; q < 4; ++q) {
        int off = l16 + q * 16;
        float4 x = xr[off];
        float4 c = cr[off];
        float4 qs;
        float t;
        t = c.x - x.x; qs.x = x.x + t; qd += t * t; { float dx = qs.x - x.x; e += dx * dx; }
        t = c.y - x.y; qs.y = x.y + t; qd += t * t; { float dx = qs.y - x.y; e += dx * dx; }
        t = c.z - x.z; qs.z = x.z + t; qd += t * t; { float dx = qs.z - x.z; e += dx * dx; }
        t = c.w - x.w; qs.w = x.w + t; qd += t * t; { float dx = qs.w - x.w; e += dx * dx; }
        qr[off] = qs;
    }
    if (l16 == 0) {
        atomicAdd(&g_counts[idx], 1);
        out_tok[row] = (float)idx;
    }
    #pragma unroll
    for (int o = 16; o; o >>= 1) {
        e  += __shfl_down_sync(0xffffffffu, e,  o);
        qd += __shfl_down_sync(0xffffffffu, qd, o);
    }
    if ((tid & 31) == 0) { sred_e[tid >> 5] = e; sred_q[tid >> 5] = qd; }
    __syncthreads();
    if (tid == 0) {
        double se = 0.0, sq = 0.0;
        #pragma unroll
        for (int w = 0; w < 8; w++) { se += (double)sred_e[w]; sq += (double)sred_q[w]; }
        atomicAdd(&g_se, se);
        atomicAdd(&g_sq, sq);
    }
}

// ===================== kernel 6: scalars =====================================
__global__ void vq_finalize_kernel(float* __restrict__ out_sc) {
    __shared__ double sh[256];
    int tid = threadIdx.x;
    double h = 0.0;
    for (int k = tid; k < K_CODES; k += 256) {
        double p = (double)g_counts[k] / (double)N_ROWS;
        h -= p * log(p + 1e-10);
    }
    sh[tid] = h;
    __syncthreads();
    for (int s = 128; s; s >>= 1) {
        if (tid < s) sh[tid] += sh[tid + s];
        __syncthreads();
    }
    if (tid == 0) {
        double nd = (double)N_ROWS * (double)DIM;
        double e_mse = g_se / nd;
        double q_mse = g_sq / nd;
        out_sc[0] = (float)(COMMITMENT_COST * e_mse + q_mse);
        out_sc[1] = (float)(COMMITMENT_COST * e_mse);
        out_sc[2] = (float)q_mse;
        out_sc[3] = (float)exp(sh[0]);
    }
}

// ===================== launch ================================================
extern "C" void kernel_launch(void* const* d_in, const int* in_sizes, int n_in,
                              void* d_out, int out_size) {
    const float* X  = (const float*)d_in[0];   // [32,1024,256] fp32
    const float* CB = (const float*)d_in[1];   // [8192,256]   fp32
    float* out     = (float*)d_out;
    float* out_q   = out;
    float* out_tok = out + (size_t)N_ROWS * DIM;
    float* out_sc  = out_tok + N_ROWS;

    cudaFuncSetAttribute(vq_argmin_mma,
                         cudaFuncAttributeMaxDynamicSharedMemorySize, ARG_SMEM);

    vq_zero_kernel<<<(N_ROWS + 255) / 256, 256>>>();
    vq_cnorm_kernel<<<K_CODES / 8, 256>>>(CB);
    vq_split_x_kernel<<<(N_ROWS * DIM / 4 + 255) / 256, 256>>>(X);
    vq_split_c_kernel<<<(K_CODES * DIM / 4 + 255) / 256, 256>>>(CB);
    vq_argmin_mma<<<1024, 256, ARG_SMEM>>>();
    vq_epilogue_kernel<<<N_ROWS / 16, 256>>>(X, CB, out_q, out_tok);
    vq_finalize_kernel<<<1, 256>>>(out_sc);
}